// round 7
// baseline (speedup 1.0000x reference)
#include <cuda_runtime.h>
#include <cuda_bf16.h>

// Problem constants
#define BATCH 32
#define CIN   256
#define COUT  256
#define NEXP  8
#define CHID  64
#define HW    3136   // 56*56

// GEMM tiling
#define BM 128
#define BN 112            // 3136 = 28 * 112
#define BK 32
#define BNP 120           // padded B row (floats) -> conflict-free B frag LDS
#define NCHUNKS (CIN / BK)
#define NSTAGES 3

// per-stage smem (floats): A frag chunk 4096 + B tile 32*120 = 3840
#define STG_FLOATS 7936
#define SM_FLOATS (NSTAGES * STG_FLOATS)   // 23808 floats = 95232 bytes

// Device scratch (allocation-free per harness rules)
__device__ float g_pooled[BATCH * CIN];
__device__ float g_attn[BATCH * NEXP];
// A in m16n8k8 fragment layout: [b][mtile 16][ksgroup 32][lane 32][reg 4]
__device__ float g_wdyn[BATCH * 16 * 32 * 32 * 4];   // 8 MB, tf32(rna)-rounded
// tf32(rna)-rounded copy of x, same layout
__device__ float g_xr[(size_t)BATCH * CIN * HW];     // 103 MB

__device__ __forceinline__ float tf32r(float f) {
    unsigned r;
    asm("cvt.rna.tf32.f32 %0, %1;" : "=r"(r) : "f"(f));
    return __uint_as_float(r);
}
__device__ __forceinline__ unsigned smem_u32(const void* p) {
    unsigned a;
    asm("{ .reg .u64 t; cvta.to.shared.u64 t, %1; cvt.u32.u64 %0, t; }" : "=r"(a) : "l"(p));
    return a;
}
__device__ __forceinline__ void cp_async16(unsigned dst, const void* src) {
    asm volatile("cp.async.cg.shared.global [%0], [%1], 16;" :: "r"(dst), "l"(src) : "memory");
}
#define CP_COMMIT() asm volatile("cp.async.commit_group;" ::: "memory")
#define CP_WAIT1()  asm volatile("cp.async.wait_group 1;" ::: "memory")
#define CP_WAIT0()  asm volatile("cp.async.wait_group 0;" ::: "memory")

__device__ __forceinline__ void mma8(float4& d, const float4& a, float b0, float b1) {
    asm volatile(
        "mma.sync.aligned.m16n8k8.row.col.f32.tf32.tf32.f32 "
        "{%0,%1,%2,%3}, {%4,%5,%6,%7}, {%8,%9}, {%0,%1,%2,%3};"
        : "+f"(d.x), "+f"(d.y), "+f"(d.z), "+f"(d.w)
        : "r"(__float_as_uint(a.x)), "r"(__float_as_uint(a.y)),
          "r"(__float_as_uint(a.z)), "r"(__float_as_uint(a.w)),
          "r"(__float_as_uint(b0)), "r"(__float_as_uint(b1)));
}

// ---------------------------------------------------------------------------
// Kernel 1: global average pool + tf32(rna)-rounded copy of x
// ---------------------------------------------------------------------------
__global__ void pool_kernel(const float* __restrict__ x) {
    const int bc = blockIdx.x;
    const float* __restrict__ p = x + (size_t)bc * HW;
    float* __restrict__ q = g_xr + (size_t)bc * HW;
    const int tid = threadIdx.x;

    float s = 0.0f;
    const float4* p4 = (const float4*)p;
    float4* q4 = (float4*)q;
    for (int i = tid; i < HW / 4; i += 256) {
        float4 v = p4[i];
        s += v.x + v.y + v.z + v.w;
        q4[i] = make_float4(tf32r(v.x), tf32r(v.y), tf32r(v.z), tf32r(v.w));
    }
    for (int off = 16; off > 0; off >>= 1)
        s += __shfl_xor_sync(0xFFFFFFFFu, s, off);

    __shared__ float red[8];
    if ((tid & 31) == 0) red[tid >> 5] = s;
    __syncthreads();
    if (tid == 0) {
        float t = 0.0f;
        #pragma unroll
        for (int w = 0; w < 8; w++) t += red[w];
        g_pooled[bc] = t * (1.0f / (float)HW);
    }
}

// ---------------------------------------------------------------------------
// Kernel 2: MLP + softmax -> attn
// ---------------------------------------------------------------------------
__global__ void attn_kernel(const float* __restrict__ w1,
                            const float* __restrict__ b1,
                            const float* __restrict__ w2,
                            const float* __restrict__ b2) {
    const int b = blockIdx.x;
    const int t = threadIdx.x;

    __shared__ float sp[CIN];
    __shared__ float sh[CHID];
    __shared__ float sl[NEXP];

    for (int i = t; i < CIN; i += 64) sp[i] = g_pooled[b * CIN + i];
    __syncthreads();

    float acc = b1[t];
    const float* w1r = w1 + t * CIN;
    #pragma unroll 8
    for (int c = 0; c < CIN; c++) acc = fmaf(w1r[c], sp[c], acc);
    sh[t] = fmaxf(acc, 0.0f);
    __syncthreads();

    if (t < NEXP) {
        float l = b2[t];
        const float* w2r = w2 + t * CHID;
        #pragma unroll
        for (int j = 0; j < CHID; j++) l = fmaf(w2r[j], sh[j], l);
        sl[t] = l;
    }
    __syncthreads();

    if (t == 0) {
        float m = sl[0];
        #pragma unroll
        for (int e = 1; e < NEXP; e++) m = fmaxf(m, sl[e]);
        float sum = 0.0f;
        float ex[NEXP];
        #pragma unroll
        for (int e = 0; e < NEXP; e++) { ex[e] = __expf(sl[e] - m); sum += ex[e]; }
        float inv = 1.0f / sum;
        #pragma unroll
        for (int e = 0; e < NEXP; e++) g_attn[b * NEXP + e] = ex[e] * inv;
    }
}

// ---------------------------------------------------------------------------
// Kernel 3: w_dyn = attn . weights, written in m16n8k8 A-fragment layout,
// tf32(rna)-rounded.  One block per co; weights read exactly once.
// ---------------------------------------------------------------------------
__global__ __launch_bounds__(256)
void wdyn_kernel(const float* __restrict__ weights) {
    const int co = blockIdx.x;
    const int ci = threadIdx.x;

    __shared__ float sw[NEXP][CIN];
    __shared__ float sa[BATCH][NEXP];

    #pragma unroll
    for (int e = 0; e < NEXP; e++)
        sw[e][ci] = weights[((size_t)e * COUT + co) * CIN + ci];
    if (ci < BATCH * NEXP)
        ((float*)sa)[ci] = g_attn[ci];
    __syncthreads();

    float w[NEXP];
    #pragma unroll
    for (int e = 0; e < NEXP; e++) w[e] = sw[e][ci];

    const int mt  = co >> 4;
    const int r   = co & 15;
    const int ksg = ci >> 3;
    const int cl  = ci & 7;
    const int lane = (r & 7) * 4 + (cl & 3);
    const int reg  = ((r >> 3) & 1) + 2 * ((cl >> 2) & 1);
    const size_t base = ((size_t)(mt * 32 + ksg) * 32 + lane) * 4 + reg;

    #pragma unroll 4
    for (int b = 0; b < BATCH; b++) {
        float s = 0.0f;
        #pragma unroll
        for (int e = 0; e < NEXP; e++) s = fmaf(sa[b][e], w[e], s);
        g_wdyn[(size_t)b * (16 * 32 * 32 * 4) + base] = tf32r(s);
    }
}

// ---------------------------------------------------------------------------
// Kernel 4: hand-rolled m16n8k8 tf32 batched GEMM, pure cp.async mainloop
//   out[b] (256 x 3136) = w_dyn[b] @ xr[b]
//   CTA 128 x 112; 8 warps (4m x 2n); warp tile 32 x 56.
//   3-stage cp.async pipeline; both operands pre-rounded to tf32 in DRAM.
// ---------------------------------------------------------------------------
__global__ __launch_bounds__(256, 2)
void gemm_mma(float* __restrict__ out) {
    extern __shared__ float sm[];
    const unsigned sbase = smem_u32(sm);

    const int tid  = threadIdx.x;
    const int wid  = tid >> 5;
    const int lane = tid & 31;
    const int wm = wid >> 1;          // 0..3  (m offset 32*wm)
    const int wn = wid & 1;           // 0..1  (n offset 56*wn)

    const int n0 = blockIdx.x * BN;
    const int mb = blockIdx.y;        // 0..1
    const int b  = blockIdx.z;

    const float* __restrict__ Afrag = g_wdyn + (size_t)(b * 16 + mb * 8) * (32 * 32 * 4);
    const float* __restrict__ Bg = g_xr + (size_t)b * CIN * HW;

    // B cp.async mapping: 896 16B units; unit u: krow=u/28, c4=(u%28)*4
    const int kr0 = tid / 28,  nc0 = (tid % 28) * 4;
    const int kr1 = (tid + 256) / 28, nc1 = ((tid + 256) % 28) * 4;
    const int kr2 = (tid + 512) / 28, nc2 = ((tid + 512) % 28) * 4;
    const int kr3 = (tid + 768) / 28, nc3 = ((tid + 768) % 28) * 4;

    float4 acc[2][7];
    #pragma unroll
    for (int i = 0; i < 2; i++)
        #pragma unroll
        for (int j = 0; j < 7; j++)
            acc[i][j] = make_float4(0.f, 0.f, 0.f, 0.f);

    // issue one chunk's cp.asyncs into stage s
    auto issue = [&](int c, int s) {
        const unsigned abase = sbase + (unsigned)(s * STG_FLOATS) * 4;
        const unsigned bbase = abase + 4096 * 4;
        #pragma unroll
        for (int i = 0; i < 4; i++) {
            const int u = tid * 4 + i;
            const int mt_l = u >> 7, ks = (u >> 5) & 3, l = u & 31;
            cp_async16(abase + (unsigned)u * 16,
                       Afrag + ((size_t)(mt_l * 32 + c * 4 + ks) * 32 + l) * 4);
        }
        const int k0 = c * BK;
        cp_async16(bbase + (unsigned)(kr0 * BNP + nc0) * 4, Bg + (size_t)(k0 + kr0) * HW + n0 + nc0);
        cp_async16(bbase + (unsigned)(kr1 * BNP + nc1) * 4, Bg + (size_t)(k0 + kr1) * HW + n0 + nc1);
        cp_async16(bbase + (unsigned)(kr2 * BNP + nc2) * 4, Bg + (size_t)(k0 + kr2) * HW + n0 + nc2);
        if (tid < 128)
            cp_async16(bbase + (unsigned)(kr3 * BNP + nc3) * 4, Bg + (size_t)(k0 + kr3) * HW + n0 + nc3);
    };

    // ---- prologue: stages 0,1 in flight ----
    issue(0, 0); CP_COMMIT();
    issue(1, 1); CP_COMMIT();

    const int kr = lane & 3;            // k row within 8-group
    const int gc = lane >> 2;           // n col within 8-tile

    for (int c = 0; c < NCHUNKS; c++) {
        if (c < NCHUNKS - 1) CP_WAIT1(); else CP_WAIT0();
        __syncthreads();                // chunk c visible; stage (c+2)%3 free

        if (c + 2 < NCHUNKS) {
            issue(c + 2, (c + 2) % NSTAGES);
            CP_COMMIT();
        }

        const float* As = sm + (c % NSTAGES) * STG_FLOATS;
        const float* Bs = As + 4096;

        #pragma unroll
        for (int ks = 0; ks < 4; ks++) {
            float4 a0 = *(const float4*)(As + ((size_t)((wm * 2 + 0) * 4 + ks) * 32 + lane) * 4);
            float4 a1 = *(const float4*)(As + ((size_t)((wm * 2 + 1) * 4 + ks) * 32 + lane) * 4);
            const float* brow0 = Bs + (ks * 8 + kr) * BNP + wn * 56 + gc;
            const float* brow1 = brow0 + 4 * BNP;
            #pragma unroll
            for (int nt = 0; nt < 7; nt++) {
                const float b0 = brow0[nt * 8];
                const float b1 = brow1[nt * 8];
                mma8(acc[0][nt], a0, b0, b1);
                mma8(acc[1][nt], a1, b0, b1);
            }
        }
    }

    // ---- epilogue: direct STG.64 per accumulator half ----
    const int r  = lane >> 2;
    const int t2 = (lane & 3) * 2;
    float* __restrict__ C = out + (size_t)b * COUT * HW
                          + (size_t)(mb * BM + wm * 32) * HW + n0 + wn * 56;
    #pragma unroll
    for (int it = 0; it < 2; it++) {
        #pragma unroll
        for (int nt = 0; nt < 7; nt++) {
            float* p0 = C + (size_t)(it * 16 + r) * HW + nt * 8 + t2;
            float* p1 = p0 + 8 * HW;
            *(float2*)p0 = make_float2(acc[it][nt].x, acc[it][nt].y);
            *(float2*)p1 = make_float2(acc[it][nt].z, acc[it][nt].w);
        }
    }
}

// ---------------------------------------------------------------------------
// Launch
// ---------------------------------------------------------------------------
extern "C" void kernel_launch(void* const* d_in, const int* in_sizes, int n_in,
                              void* d_out, int out_size) {
    const float* x       = (const float*)d_in[0];
    const float* weights = (const float*)d_in[1];
    const float* w1      = (const float*)d_in[2];
    const float* b1      = (const float*)d_in[3];
    const float* w2      = (const float*)d_in[4];
    const float* b2      = (const float*)d_in[5];
    float* out = (float*)d_out;

    pool_kernel<<<BATCH * CIN, 256>>>(x);
    attn_kernel<<<BATCH, 64>>>(w1, b1, w2, b2);
    wdyn_kernel<<<COUT, 256>>>(weights);

    cudaFuncSetAttribute(gemm_mma, cudaFuncAttributeMaxDynamicSharedMemorySize,
                         SM_FLOATS * (int)sizeof(float));
    dim3 grid(HW / BN, COUT / BM, BATCH);   // 28 x 2 x 32
    gemm_mma<<<grid, 256, SM_FLOATS * sizeof(float)>>>(out);
}

// round 8
// speedup vs baseline: 1.4645x; 1.4645x over previous
#include <cuda_runtime.h>
#include <cuda_fp16.h>

// Problem constants
#define BATCH 32
#define CIN   256
#define COUT  256
#define NEXP  8
#define CHID  64
#define HW    3136   // 56*56

// GEMM tiling
#define BM 128
#define BN 112            // 3136 = 28 * 112
#define BK 32             // 2 k-steps of 16
#define BNP2 120          // padded B row (halves): 240B stride, ldmatrix conflict-free
#define NCHUNKS (CIN / BK)
#define NSTAGES 4

// per-stage smem bytes: A = 8 mt * 2 ks * 32 lane * 16B = 8192; B = 32 * 240 = 7680
#define A_BYTES 8192
#define STG_BYTES 15872
#define SM_BYTES (NSTAGES * STG_BYTES)   // 63488

// Device scratch (allocation-free per harness rules)
__device__ float g_pooled[BATCH * CIN];
__device__ float g_attn[BATCH * NEXP];
// A (w_dyn) in fp16 m16n8k16 A-fragment layout: [b][mt 16][kstep 16][lane 32][8 halves]
__device__ __half g_wh[BATCH * 16 * 16 * 32 * 8];        // 4 MB
// fp16 copy of x, same layout as x
__device__ __half g_xh[(size_t)BATCH * CIN * HW];        // 52 MB

__device__ __forceinline__ unsigned smem_u32(const void* p) {
    unsigned a;
    asm("{ .reg .u64 t; cvta.to.shared.u64 t, %1; cvt.u32.u64 %0, t; }" : "=r"(a) : "l"(p));
    return a;
}
__device__ __forceinline__ void cp_async16(unsigned dst, const void* src) {
    asm volatile("cp.async.cg.shared.global [%0], [%1], 16;" :: "r"(dst), "l"(src) : "memory");
}
#define CP_COMMIT() asm volatile("cp.async.commit_group;" ::: "memory")
#define CP_WAIT2()  asm volatile("cp.async.wait_group 2;" ::: "memory")
#define CP_WAIT1()  asm volatile("cp.async.wait_group 1;" ::: "memory")
#define CP_WAIT0()  asm volatile("cp.async.wait_group 0;" ::: "memory")

__device__ __forceinline__ void lds128(unsigned* r, unsigned addr) {
    asm volatile("ld.shared.v4.b32 {%0,%1,%2,%3}, [%4];"
                 : "=r"(r[0]), "=r"(r[1]), "=r"(r[2]), "=r"(r[3]) : "r"(addr));
}
__device__ __forceinline__ void ldmx2t(unsigned& b0, unsigned& b1, unsigned addr) {
    asm volatile("ldmatrix.sync.aligned.m8n8.x2.trans.shared.b16 {%0,%1}, [%2];"
                 : "=r"(b0), "=r"(b1) : "r"(addr));
}
__device__ __forceinline__ void mma16(float4& d, const unsigned* a, unsigned b0, unsigned b1) {
    asm volatile(
        "mma.sync.aligned.m16n8k16.row.col.f32.f16.f16.f32 "
        "{%0,%1,%2,%3}, {%4,%5,%6,%7}, {%8,%9}, {%0,%1,%2,%3};"
        : "+f"(d.x), "+f"(d.y), "+f"(d.z), "+f"(d.w)
        : "r"(a[0]), "r"(a[1]), "r"(a[2]), "r"(a[3]), "r"(b0), "r"(b1));
}

// ---------------------------------------------------------------------------
// Kernel 1: global average pool + fp16 copy of x
// ---------------------------------------------------------------------------
__global__ void pool_kernel(const float* __restrict__ x) {
    const int bc = blockIdx.x;
    const float* __restrict__ p = x + (size_t)bc * HW;
    __half2* __restrict__ q2 = (__half2*)(g_xh + (size_t)bc * HW);
    const int tid = threadIdx.x;

    float s = 0.0f;
    const float4* p4 = (const float4*)p;
    for (int i = tid; i < HW / 4; i += 256) {
        float4 v = p4[i];
        s += v.x + v.y + v.z + v.w;
        q2[i * 2]     = __floats2half2_rn(v.x, v.y);
        q2[i * 2 + 1] = __floats2half2_rn(v.z, v.w);
    }
    for (int off = 16; off > 0; off >>= 1)
        s += __shfl_xor_sync(0xFFFFFFFFu, s, off);

    __shared__ float red[8];
    if ((tid & 31) == 0) red[tid >> 5] = s;
    __syncthreads();
    if (tid == 0) {
        float t = 0.0f;
        #pragma unroll
        for (int w = 0; w < 8; w++) t += red[w];
        g_pooled[bc] = t * (1.0f / (float)HW);
    }
}

// ---------------------------------------------------------------------------
// Kernel 2: MLP + softmax -> attn
// ---------------------------------------------------------------------------
__global__ void attn_kernel(const float* __restrict__ w1,
                            const float* __restrict__ b1,
                            const float* __restrict__ w2,
                            const float* __restrict__ b2) {
    const int b = blockIdx.x;
    const int t = threadIdx.x;

    __shared__ float sp[CIN];
    __shared__ float sh[CHID];
    __shared__ float sl[NEXP];

    for (int i = t; i < CIN; i += 64) sp[i] = g_pooled[b * CIN + i];
    __syncthreads();

    float acc = b1[t];
    const float* w1r = w1 + t * CIN;
    #pragma unroll 8
    for (int c = 0; c < CIN; c++) acc = fmaf(w1r[c], sp[c], acc);
    sh[t] = fmaxf(acc, 0.0f);
    __syncthreads();

    if (t < NEXP) {
        float l = b2[t];
        const float* w2r = w2 + t * CHID;
        #pragma unroll
        for (int j = 0; j < CHID; j++) l = fmaf(w2r[j], sh[j], l);
        sl[t] = l;
    }
    __syncthreads();

    if (t == 0) {
        float m = sl[0];
        #pragma unroll
        for (int e = 1; e < NEXP; e++) m = fmaxf(m, sl[e]);
        float sum = 0.0f;
        float ex[NEXP];
        #pragma unroll
        for (int e = 0; e < NEXP; e++) { ex[e] = __expf(sl[e] - m); sum += ex[e]; }
        float inv = 1.0f / sum;
        #pragma unroll
        for (int e = 0; e < NEXP; e++) g_attn[b * NEXP + e] = ex[e] * inv;
    }
}

// ---------------------------------------------------------------------------
// Kernel 3: w_dyn = attn . weights, fp16, written in m16n8k16 A-fragment layout.
// Element (co, ci): mt=co>>4, r=co&15, kstep=ci>>4, kk=ci&15
//   lane = (r&7)*4 + ((kk>>1)&3)
//   reg  = ((r>>3)&1) + 2*((kk>>3)&1)
//   half = kk&1
// ---------------------------------------------------------------------------
__global__ __launch_bounds__(256)
void wdyn_kernel(const float* __restrict__ weights) {
    const int co = blockIdx.x;
    const int ci = threadIdx.x;

    __shared__ float sw[NEXP][CIN];
    __shared__ float sa[BATCH][NEXP];

    #pragma unroll
    for (int e = 0; e < NEXP; e++)
        sw[e][ci] = weights[((size_t)e * COUT + co) * CIN + ci];
    if (ci < BATCH * NEXP)
        ((float*)sa)[ci] = g_attn[ci];
    __syncthreads();

    float w[NEXP];
    #pragma unroll
    for (int e = 0; e < NEXP; e++) w[e] = sw[e][ci];

    const int mt    = co >> 4;
    const int r     = co & 15;
    const int kstep = ci >> 4;
    const int kk    = ci & 15;
    const int lane  = (r & 7) * 4 + ((kk >> 1) & 3);
    const int reg   = ((r >> 3) & 1) + 2 * ((kk >> 3) & 1);
    const int half  = kk & 1;
    const size_t base = ((size_t)(mt * 16 + kstep) * 32 + lane) * 8 + reg * 2 + half;

    #pragma unroll 4
    for (int b = 0; b < BATCH; b++) {
        float s = 0.0f;
        #pragma unroll
        for (int e = 0; e < NEXP; e++) s = fmaf(sa[b][e], w[e], s);
        g_wh[(size_t)b * (16 * 16 * 32 * 8) + base] = __float2half(s);
    }
}

// ---------------------------------------------------------------------------
// Kernel 4: fp16 m16n8k16 batched GEMM, pure cp.async mainloop
//   out[b] (256 x 3136) = w_dyn[b] @ x[b]  (both fp16, fp32 accumulate)
//   CTA 128 x 112; 8 warps (4m x 2n); warp tile 32 x 56.
//   A: fragment-layout cp.async -> 1 LDS.128 per fragment.
//   B: row-major fp16 smem -> ldmatrix.x2.trans per 16k x 8n tile.
// ---------------------------------------------------------------------------
__global__ __launch_bounds__(256, 2)
void gemm_mma(float* __restrict__ out) {
    extern __shared__ char smc[];
    const unsigned sbase = smem_u32(smc);

    const int tid  = threadIdx.x;
    const int wid  = tid >> 5;
    const int lane = tid & 31;
    const int wm = wid >> 1;          // 0..3  (m offset 32*wm)
    const int wn = wid & 1;           // 0..1  (n offset 56*wn)

    const int n0 = blockIdx.x * BN;
    const int mb = blockIdx.y;        // 0..1
    const int b  = blockIdx.z;

    // A fragment source: mtiles mb*8 .. mb*8+7, 16 ksteps each
    const __half* __restrict__ Afrag = g_wh + (size_t)(b * 16 + mb * 8) * (16 * 32 * 8);
    const __half* __restrict__ Bg = g_xh + (size_t)b * CIN * HW;

    // B cp.async mapping: 448 16B units (32 rows x 14 units)
    const int kr0 = tid / 14,  nc0 = tid % 14;
    const int kr1 = (tid + 256) / 14, nc1 = (tid + 256) % 14;   // tid < 192

    float4 acc[2][7];
    #pragma unroll
    for (int i = 0; i < 2; i++)
        #pragma unroll
        for (int j = 0; j < 7; j++)
            acc[i][j] = make_float4(0.f, 0.f, 0.f, 0.f);

    auto issue = [&](int c, int s) {
        const unsigned abase = sbase + (unsigned)(s * STG_BYTES);
        const unsigned bbase = abase + A_BYTES;
        // A: 512 units; 2 per thread.  unit u: mt=u>>6, ks=(u>>5)&1, l=u&31
        #pragma unroll
        for (int i = 0; i < 2; i++) {
            const int u = tid * 2 + i;
            const int mt = u >> 6, ks = (u >> 5) & 1, l = u & 31;
            cp_async16(abase + (unsigned)u * 16,
                       Afrag + ((size_t)(mt * 16 + 2 * c + ks) * 32 + l) * 8);
        }
        const int k0 = c * BK;
        cp_async16(bbase + (unsigned)(kr0 * 240 + nc0 * 16),
                   Bg + (size_t)(k0 + kr0) * HW + n0 + nc0 * 8);
        if (tid < 192)
            cp_async16(bbase + (unsigned)(kr1 * 240 + nc1 * 16),
                       Bg + (size_t)(k0 + kr1) * HW + n0 + nc1 * 8);
    };

    // ---- prologue: 3 stages in flight ----
    issue(0, 0); CP_COMMIT();
    issue(1, 1); CP_COMMIT();
    issue(2, 2); CP_COMMIT();

    // per-lane ldmatrix row offset (bytes): row (lane&15) within 16-k group + n base
    const unsigned bRow = (unsigned)((lane & 15) * 240 + wn * 112);

    for (int c = 0; c < NCHUNKS; c++) {
        if (c < NCHUNKS - 2) CP_WAIT2();
        else if (c == NCHUNKS - 2) CP_WAIT1();
        else CP_WAIT0();
        __syncthreads();

        if (c + 3 < NCHUNKS) { issue(c + 3, (c + 3) % NSTAGES); CP_COMMIT(); }

        const unsigned aS = sbase + (unsigned)((c % NSTAGES) * STG_BYTES);
        const unsigned bS = aS + A_BYTES;

        #pragma unroll
        for (int ks = 0; ks < 2; ks++) {
            unsigned a0[4], a1[4];
            lds128(a0, aS + (unsigned)((((wm * 2 + 0) * 2 + ks) * 32 + lane) * 16));
            lds128(a1, aS + (unsigned)((((wm * 2 + 1) * 2 + ks) * 32 + lane) * 16));
            const unsigned bk = bS + (unsigned)(ks * 16 * 240) + bRow;
            #pragma unroll
            for (int nt = 0; nt < 7; nt++) {
                unsigned b0, b1;
                ldmx2t(b0, b1, bk + (unsigned)(nt * 16));
                mma16(acc[0][nt], a0, b0, b1);
                mma16(acc[1][nt], a1, b0, b1);
            }
        }
    }

    // ---- epilogue: direct STG.64 per accumulator half ----
    const int r  = lane >> 2;
    const int t2 = (lane & 3) * 2;
    float* __restrict__ C = out + (size_t)b * COUT * HW
                          + (size_t)(mb * BM + wm * 32) * HW + n0 + wn * 56;
    #pragma unroll
    for (int it = 0; it < 2; it++) {
        #pragma unroll
        for (int nt = 0; nt < 7; nt++) {
            float* p0 = C + (size_t)(it * 16 + r) * HW + nt * 8 + t2;
            float* p1 = p0 + 8 * HW;
            *(float2*)p0 = make_float2(acc[it][nt].x, acc[it][nt].y);
            *(float2*)p1 = make_float2(acc[it][nt].z, acc[it][nt].w);
        }
    }
}

// ---------------------------------------------------------------------------
// Launch
// ---------------------------------------------------------------------------
extern "C" void kernel_launch(void* const* d_in, const int* in_sizes, int n_in,
                              void* d_out, int out_size) {
    const float* x       = (const float*)d_in[0];
    const float* weights = (const float*)d_in[1];
    const float* w1      = (const float*)d_in[2];
    const float* b1      = (const float*)d_in[3];
    const float* w2      = (const float*)d_in[4];
    const float* b2      = (const float*)d_in[5];
    float* out = (float*)d_out;

    pool_kernel<<<BATCH * CIN, 256>>>(x);
    attn_kernel<<<BATCH, 64>>>(w1, b1, w2, b2);
    wdyn_kernel<<<COUT, 256>>>(weights);

    cudaFuncSetAttribute(gemm_mma, cudaFuncAttributeMaxDynamicSharedMemorySize, SM_BYTES);
    dim3 grid(HW / BN, COUT / BM, BATCH);   // 28 x 2 x 32
    gemm_mma<<<grid, 256, SM_BYTES>>>(out);
}